// round 12
// baseline (speedup 1.0000x reference)
#include <cuda_runtime.h>
#include <cuda_bf16.h>
#include <float.h>
#include <stdint.h>

#define BN 4096
#define KN 32768
#define DN 128
#define HN 3
#define MTILE 128
#define NTILE 128
#define NTILES (KN / NTILE)          // 256
#define NS 4                         // k-splits -> grid (32,4) = 128 CTAs
#define TPB 256
#define TILES_PER_CTA (KN / NS / NTILE)  // 64
#define AST 136                      // A smem row stride (bf16)
#define BST 136                      // B smem row stride (bf16)

// smem byte offsets (dynamic)
#define SM_A    0
#define SM_B0   34816
#define SM_B1   69632
#define SM_WNS  104448               // float[2][128]
#define SM_TMIN 105472               // float[2][128]
#define SM_TOT  106496

// ---------------- scratch (static; no allocations) ----------------
__device__ float g_resid[BN * DN];
__device__ float g_quant[BN * DN];
__device__ float g_rnorm[BN];
__device__ float g_wnorm[HN * KN];
__device__ uint4 g_embh[(size_t)HN * KN * 16];   // bf16 rows, 16B units
__device__ uint4 g_residh[BN * 16];
__device__ float g_tmin[(size_t)BN * NTILES];
__device__ int   g_codes[BN * HN];
__device__ int   g_wmaxb[HN];

// ---------------- PTX helpers (baseline sm_80+ features only) ----------------
__device__ __forceinline__ uint32_t smem_to_u32(const void* p) {
    uint32_t a;
    asm("{ .reg .u64 t; cvta.to.shared.u64 t, %1; cvt.u32.u64 %0, t; }" : "=r"(a) : "l"(p));
    return a;
}
__device__ __forceinline__ void ldm_x4(uint32_t* r, uint32_t addr) {
    asm volatile("ldmatrix.sync.aligned.m8n8.x4.shared.b16 {%0,%1,%2,%3}, [%4];"
        : "=r"(r[0]), "=r"(r[1]), "=r"(r[2]), "=r"(r[3]) : "r"(addr));
}
__device__ __forceinline__ void ldm_x2(uint32_t* r, uint32_t addr) {
    asm volatile("ldmatrix.sync.aligned.m8n8.x2.shared.b16 {%0,%1}, [%2];"
        : "=r"(r[0]), "=r"(r[1]) : "r"(addr));
}
__device__ __forceinline__ void mma16816(float* d, const uint32_t* a, const uint32_t* b) {
    asm volatile("mma.sync.aligned.m16n8k16.row.col.f32.bf16.bf16.f32 "
        "{%0,%1,%2,%3}, {%4,%5,%6,%7}, {%8,%9}, {%0,%1,%2,%3};"
        : "+f"(d[0]), "+f"(d[1]), "+f"(d[2]), "+f"(d[3])
        : "r"(a[0]), "r"(a[1]), "r"(a[2]), "r"(a[3]), "r"(b[0]), "r"(b[1]));
}
__device__ __forceinline__ void cp_async16(uint32_t smem_addr, const void* gptr) {
    asm volatile("cp.async.cg.shared.global [%0], [%1], 16;" :: "r"(smem_addr), "l"(gptr));
}
#define CP_COMMIT() asm volatile("cp.async.commit_group;" ::: "memory")
#define CP_WAIT1()  asm volatile("cp.async.wait_group 1;" ::: "memory")
#define CP_WAIT0()  asm volatile("cp.async.wait_group 0;" ::: "memory")

// pack two fp32 to bf16x2 (lo = x, hi = y), round-to-nearest
__device__ __forceinline__ uint32_t bf16x2_rn(float x, float y) {
    uint32_t r;
    asm("cvt.rn.bf16x2.f32 %0, %1, %2;" : "=r"(r) : "f"(y), "f"(x));
    return r;
}

// ---------------------------------------------------------------------------
// XLA-style exact row sum(x*x): separate mul/add roundings + shfl tree.
__device__ __forceinline__ float row_sumsq_xla(const float* __restrict__ x, int lane) {
    float acc = 0.0f;
    #pragma unroll
    for (int i = 0; i < 4; i++) {
        float v = x[lane + 32 * i];
        acc = __fadd_rn(acc, __fmul_rn(v, v));
    }
    #pragma unroll
    for (int o = 16; o; o >>= 1)
        acc = __fadd_rn(acc, __shfl_down_sync(0xffffffffu, acc, o));
    return acc;
}

__global__ void prep_kernel(const float* __restrict__ in) {
    int i = blockIdx.x * blockDim.x + threadIdx.x;
    if (i < BN * DN) { g_resid[i] = in[i]; g_quant[i] = 0.0f; }
    if (i < HN) g_wmaxb[i] = 0;
}

__global__ void wnorm_kernel(const float* __restrict__ emb) {
    int row  = blockIdx.x * 8 + (threadIdx.x >> 5);
    int lane = threadIdx.x & 31;
    if (row >= HN * KN) return;
    float s = row_sumsq_xla(emb + (size_t)row * DN, lane);
    if (lane == 0) {
        g_wnorm[row] = s;
        atomicMax(&g_wmaxb[row / KN], __float_as_int(s));  // s > 0
    }
}

__global__ void rnorm_kernel() {
    int row  = blockIdx.x * 8 + (threadIdx.x >> 5);
    int lane = threadIdx.x & 31;
    if (row >= BN) return;
    float s = row_sumsq_xla(g_resid + (size_t)row * DN, lane);
    if (lane == 0) g_rnorm[row] = s;
}

// fp32 -> packed bf16 (screening operands only)
__global__ void emb_cvt_kernel(const float* __restrict__ emb) {
    size_t i = (size_t)blockIdx.x * blockDim.x + threadIdx.x;
    if (i >= (size_t)HN * KN * 16) return;
    const float4* s = (const float4*)(emb + i * 8);
    float4 a = s[0], b = s[1];
    g_embh[i] = make_uint4(bf16x2_rn(a.x, a.y), bf16x2_rn(a.z, a.w),
                           bf16x2_rn(b.x, b.y), bf16x2_rn(b.z, b.w));
}
__global__ void resid_cvt_kernel() {
    int i = blockIdx.x * blockDim.x + threadIdx.x;
    if (i >= BN * 16) return;
    const float4* s = (const float4*)(g_resid + (size_t)i * 8);
    float4 a = s[0], b = s[1];
    g_residh[i] = make_uint4(bf16x2_rn(a.x, a.y), bf16x2_rn(a.z, a.w),
                             bf16x2_rn(b.x, b.y), bf16x2_rn(b.z, b.w));
}

// ---------------------------------------------------------------------------
// Screening: bf16 warp-MMA (m16n8k16). 128 rows x 128 codes per tile; 8 warps
// in a 4(M) x 2(N) layout, warp tile 32x64. Per-(row,tile) min of wn - 2*dot
// goes to g_tmin. Approximate by design — exact rescore follows.
__global__ __launch_bounds__(TPB)
void screen_kernel(int h) {
    extern __shared__ char dsm[];
    const uint32_t sbase = smem_to_u32(dsm);
    float* wns  = (float*)(dsm + SM_WNS);    // [2][128]
    float* tmb  = (float*)(dsm + SM_TMIN);   // [2][128]

    const int tid  = threadIdx.x;
    const int lane = tid & 31, wid = tid >> 5;
    const int wm = wid >> 1, wn_ = wid & 1;      // warp row-block / col-half
    const int mBase = blockIdx.x * MTILE;
    const int tile0 = blockIdx.y * TILES_PER_CTA;

    // ---- stage A (resid bf16) once: [128 rows][AST] ----
    #pragma unroll
    for (int i = 0; i < 8; i++) {
        int item = tid + TPB * i;            // 0..2047
        int r  = item >> 4;                  // 0..127
        int k8 = item & 15;                  // 16B unit
        cp_async16(sbase + SM_A + (uint32_t)(r * AST + k8 * 8) * 2,
                   &g_residh[(size_t)(mBase + r) * 16 + k8]);
    }
    CP_COMMIT();

    // ---- prefetch B tile 0 ----
    {
        const int kBase = tile0 * NTILE;
        #pragma unroll
        for (int i = 0; i < 8; i++) {
            int item = tid + TPB * i;
            int c  = item >> 4;
            int k8 = item & 15;
            cp_async16(sbase + SM_B0 + (uint32_t)(c * BST + k8 * 8) * 2,
                       &g_embh[((size_t)h * KN + kBase + c) * 16 + k8]);
        }
        CP_COMMIT();
    }

    for (int t = 0; t < TILES_PER_CTA; t++) {
        const int kTile = tile0 + t;
        const int buf = t & 1;

        // prefetch next tile
        if (t + 1 < TILES_PER_CTA) {
            const int kB2 = (tile0 + t + 1) * NTILE;
            const uint32_t bdst = sbase + (((t + 1) & 1) ? SM_B1 : SM_B0);
            #pragma unroll
            for (int i = 0; i < 8; i++) {
                int item = tid + TPB * i;
                int c  = item >> 4;
                int k8 = item & 15;
                cp_async16(bdst + (uint32_t)(c * BST + k8 * 8) * 2,
                           &g_embh[((size_t)h * KN + kB2 + c) * 16 + k8]);
            }
            CP_COMMIT();
            if (tid < 128) wns[buf * 128 + tid] = g_wnorm[h * KN + kTile * NTILE + tid];
            CP_WAIT1();
        } else {
            if (tid < 128) wns[buf * 128 + tid] = g_wnorm[h * KN + kTile * NTILE + tid];
            CP_WAIT0();
        }
        __syncthreads();   // B[buf], A (t==0), wns[buf] visible

        // ---- MMA over this tile ----
        const uint32_t a_base = sbase + SM_A;
        const uint32_t b_base = sbase + (buf ? SM_B1 : SM_B0);
        float acc[2][8][4];
        #pragma unroll
        for (int mt = 0; mt < 2; mt++)
            #pragma unroll
            for (int nt = 0; nt < 8; nt++)
                #pragma unroll
                for (int j = 0; j < 4; j++) acc[mt][nt][j] = 0.0f;

        #pragma unroll
        for (int ks = 0; ks < 8; ks++) {
            const int k0 = ks * 16;
            uint32_t af[2][4];
            #pragma unroll
            for (int mt = 0; mt < 2; mt++) {
                int row = 32 * wm + mt * 16 + (lane & 15);
                int col = k0 + (lane >> 4) * 8;
                ldm_x4(af[mt], a_base + (uint32_t)(row * AST + col) * 2);
            }
            uint32_t bf[8][2];
            #pragma unroll
            for (int nt = 0; nt < 8; nt++) {
                int n   = 64 * wn_ + nt * 8 + (lane & 7);
                int col = k0 + ((lane >> 3) & 1) * 8;
                ldm_x2(bf[nt], b_base + (uint32_t)(n * BST + col) * 2);
            }
            #pragma unroll
            for (int mt = 0; mt < 2; mt++)
                #pragma unroll
                for (int nt = 0; nt < 8; nt++)
                    mma16816(acc[mt][nt], af[mt], bf[nt]);
        }

        // ---- epilogue: per-row min of (wn - 2*dot) over warp's 64 codes ----
        #pragma unroll
        for (int mt = 0; mt < 2; mt++) {
            float r0min = FLT_MAX, r1min = FLT_MAX;
            #pragma unroll
            for (int nt = 0; nt < 8; nt++) {
                int cb = 64 * wn_ + nt * 8 + (lane & 3) * 2;
                float w0 = wns[buf * 128 + cb];
                float w1 = wns[buf * 128 + cb + 1];
                r0min = fminf(r0min, fminf(w0 - 2.0f * acc[mt][nt][0], w1 - 2.0f * acc[mt][nt][1]));
                r1min = fminf(r1min, fminf(w0 - 2.0f * acc[mt][nt][2], w1 - 2.0f * acc[mt][nt][3]));
            }
            r0min = fminf(r0min, __shfl_xor_sync(0xffffffffu, r0min, 1));
            r0min = fminf(r0min, __shfl_xor_sync(0xffffffffu, r0min, 2));
            r1min = fminf(r1min, __shfl_xor_sync(0xffffffffu, r1min, 1));
            r1min = fminf(r1min, __shfl_xor_sync(0xffffffffu, r1min, 2));
            if ((lane & 3) == 0) {
                int rl = 32 * wm + mt * 16 + (lane >> 2);
                tmb[wn_ * 128 + rl]     = r0min;
                tmb[wn_ * 128 + rl + 8] = r1min;
            }
        }
        __syncthreads();
        if (tid < 128)
            g_tmin[(size_t)(mBase + tid) * NTILES + kTile] = fminf(tmb[tid], tmb[128 + tid]);
        __syncthreads();
    }
}

// ---------------------------------------------------------------------------
// Exact rescore: per row, rescan tiles with tmin <= gmin + margin using the
// reference-exact score (k-ascending FFMA chain; fsub(fadd(rn,wn), 2*dot));
// argmin with lowest-index ties. margin >> bf16 screening error => sound.
__global__ __launch_bounds__(128)
void rescore_kernel(const float* __restrict__ emb, int h) {
    const int row = blockIdx.x, tid = threadIdx.x;
    __shared__ float rrow[DN];
    __shared__ float tm[NTILES];
    __shared__ float red[128];
    __shared__ float sv[128];
    __shared__ int   si[128];

    rrow[tid]     = g_resid[(size_t)row * DN + tid];
    tm[tid]       = g_tmin[(size_t)row * NTILES + tid];
    tm[tid + 128] = g_tmin[(size_t)row * NTILES + tid + 128];
    __syncthreads();

    red[tid] = fminf(tm[tid], tm[tid + 128]);
    __syncthreads();
    #pragma unroll
    for (int o = 64; o; o >>= 1) {
        if (tid < o) red[tid] = fminf(red[tid], red[tid + o]);
        __syncthreads();
    }
    const float gmin = red[0];
    const float rn = g_rnorm[row];
    const float wmax = sqrtf(__int_as_float(g_wmaxb[h]));
    const float margin = 0.02f * sqrtf(rn) * wmax + 1e-3f;

    float bv = FLT_MAX; int bi = 0x7fffffff;
    const float* W  = emb + (size_t)h * KN * DN;
    const float* wn = g_wnorm + h * KN;

    for (int t = 0; t < NTILES; t++) {
        if (tm[t] <= gmin + margin) {
            const int c = t * NTILE + tid;       // ascending per thread over t
            const float* wr = W + (size_t)c * DN;
            float acc = 0.0f;
            #pragma unroll 8
            for (int k = 0; k < DN; k++)
                acc = __fmaf_rn(rrow[k], wr[k], acc);   // exact reference chain
            float s = __fsub_rn(__fadd_rn(rn, wn[c]), __fmul_rn(2.0f, acc));
            if (s < bv) { bv = s; bi = c; }             // strict: lowest idx per thread
        }
    }
    sv[tid] = bv; si[tid] = bi;
    __syncthreads();
    if (tid == 0) {
        float b = FLT_MAX; int bidx = 0x7fffffff;
        #pragma unroll 4
        for (int t2 = 0; t2 < 128; t2++) {
            float v = sv[t2]; int ii = si[t2];
            if (v < b || (v == b && ii < bidx)) { b = v; bidx = ii; }
        }
        g_codes[row * HN + h] = bidx;
    }
}

// ---------------------------------------------------------------------------
__global__ void update_kernel(const float* __restrict__ emb, int h) {
    int row = blockIdx.x;
    int c = g_codes[row * HN + h];
    float q = emb[(size_t)h * KN * DN + (size_t)c * DN + threadIdx.x];
    g_resid[(size_t)row * DN + threadIdx.x] = __fsub_rn(g_resid[(size_t)row * DN + threadIdx.x], q);
    g_quant[(size_t)row * DN + threadIdx.x] = __fadd_rn(g_quant[(size_t)row * DN + threadIdx.x], q);
}

__global__ void pack_kernel(float* __restrict__ out) {
    int i = blockIdx.x * blockDim.x + threadIdx.x;
    const int q0 = BN;
    const int c0 = BN + BN * DN;
    const int tot = c0 + BN * HN;
    if (i >= tot) return;
    if (i < q0)       out[i] = 0.0f;
    else if (i < c0)  out[i] = g_quant[i - q0];
    else              out[i] = (float)g_codes[i - c0];
}

// ---------------------------------------------------------------------------
extern "C" void kernel_launch(void* const* d_in, const int* in_sizes, int n_in,
                              void* d_out, int out_size) {
    const float* inputs = (const float*)d_in[0];   // (4096,1,128) fp32
    const float* emb    = (const float*)d_in[1];   // (3,32768,128) fp32
    float* out = (float*)d_out;

    cudaFuncSetAttribute(screen_kernel, cudaFuncAttributeMaxDynamicSharedMemorySize, SM_TOT);

    prep_kernel<<<(BN * DN + 255) / 256, 256>>>(inputs);
    wnorm_kernel<<<(HN * KN) / 8, 256>>>(emb);
    {
        size_t n = (size_t)HN * KN * 16;
        emb_cvt_kernel<<<(unsigned)((n + 255) / 256), 256>>>(emb);
    }

    for (int h = 0; h < HN; h++) {
        rnorm_kernel<<<BN / 8, 256>>>();                 // exact XLA ||r||^2
        resid_cvt_kernel<<<(BN * 16) / 256, 256>>>();    // bf16 A operand
        screen_kernel<<<dim3(BN / MTILE, NS), TPB, SM_TOT>>>(h);
        rescore_kernel<<<BN, 128>>>(emb, h);
        update_kernel<<<BN, 128>>>(emb, h);
    }

    const int tot = BN + BN * DN + BN * HN;
    pack_kernel<<<(tot + 255) / 256, 256>>>(out);
}